// round 13
// baseline (speedup 1.0000x reference)
#include <cuda_runtime.h>
#include <math.h>
#include <cstdint>

#define N_NODES 200000
#define N_EDGES 1250000
#define N_GRAPHS 2048
#define IN_CH 128
#define HID 64
#define EMB 32

// ---------------- scratch (static device globals; no allocation) ----------------
__device__ int   g_is64;
__device__ int   g_deg[N_NODES];
__device__ float g_dis[N_NODES];
__device__ int   g_off[N_NODES];
__device__ int   g_cur[N_NODES];
__device__ __align__(16) int2 g_csr2[N_EDGES];   // (src, __float_as_int(dis[src]))
__device__ int   g_bsums[256];
__device__ __align__(16) float g_h1[(size_t)N_NODES * 64];
__device__ __align__(16) float g_h2[(size_t)N_NODES * 64];

__device__ __forceinline__ long long load_idx(const void* p, long long i, int is64) {
    if (is64) return ((const long long*)p)[i];
    return (long long)((const int*)p)[i];
}

// ---------------- zero degree + dtype detect (fused) ----------------
__global__ void k_zero_detect(const unsigned* __restrict__ ei_words) {
    int i = blockIdx.x * 1024 + threadIdx.x;
    if (i < N_NODES) g_deg[i] = 0;
    if (blockIdx.x == 0 && threadIdx.x < 128) {
        unsigned w = ei_words[2 * threadIdx.x + 1];
        unsigned any = __ballot_sync(0xffffffffu, w != 0u);
        __shared__ unsigned s_any[4];
        if ((threadIdx.x & 31) == 0) s_any[threadIdx.x >> 5] = any;
        __syncthreads();
        if (threadIdx.x == 0) {
            unsigned t = s_any[0] | s_any[1] | s_any[2] | s_any[3];
            g_is64 = t ? 0 : 1;
        }
    }
}

// ---------------- block inclusive scan ----------------
template <int NT>
__device__ __forceinline__ int block_inclusive_scan(int v, int tid) {
    int lane = tid & 31, w = tid >> 5;
    int x = v;
#pragma unroll
    for (int o = 1; o < 32; o <<= 1) {
        int y = __shfl_up_sync(0xffffffffu, x, o);
        if (lane >= o) x += y;
    }
    __shared__ int wsum[NT / 32];
    if (lane == 31) wsum[w] = x;
    __syncthreads();
    if (w == 0) {
        const int NW = NT / 32;
        int s = (lane < NW) ? wsum[lane] : 0;
#pragma unroll
        for (int o = 1; o < 32; o <<= 1) {
            int y = __shfl_up_sync(0xffffffffu, s, o);
            if (lane >= o) s += y;
        }
        if (lane < NW) wsum[lane] = s;
    }
    __syncthreads();
    return x + (w ? wsum[w - 1] : 0);
}

// ---------------- graph preprocessing ----------------
__global__ void k_scan1() {
    int idx = blockIdx.x * 1024 + threadIdx.x;
    int v = (idx < N_NODES) ? g_deg[idx] : 0;
    int incl = block_inclusive_scan<1024>(v, threadIdx.x);
    if (idx < N_NODES) g_off[idx] = incl - v;
    if (threadIdx.x == 1023) g_bsums[blockIdx.x] = incl;
}

// scan3': per-block inline prefix over bsums (removes the scan2 launch).
__global__ void k_scan3() {
    const int pb = blockIdx.x >> 2;   // which 1024-chunk this 256-block lies in
    __shared__ int s_pre;
    if (threadIdx.x < 32) {
        int acc = 0;
        for (int t = threadIdx.x; t < pb; t += 32) acc += g_bsums[t];
#pragma unroll
        for (int o = 16; o > 0; o >>= 1) acc += __shfl_down_sync(0xffffffffu, acc, o);
        if (threadIdx.x == 0) s_pre = acc;
    }
    __syncthreads();
    int idx = blockIdx.x * 256 + threadIdx.x;
    if (idx < N_NODES) {
        int o = g_off[idx] + s_pre;
        g_off[idx] = o;
        g_cur[idx] = o;
        g_dis[idx] = rsqrtf(1.0f + (float)g_deg[idx]);
    }
}

// fill CSR with packed (src, dis[src])
__global__ void k_fill_csr(const void* __restrict__ ei) {
    int e = blockIdx.x * 256 + threadIdx.x;
    int is64 = g_is64;
    if (e < N_EDGES) {
        int s = (int)load_idx(ei, e, is64);
        int d = (int)load_idx(ei, (long long)N_EDGES + e, is64);
        if (d >= 0 && d < N_NODES && s >= 0 && s < N_NODES) {
            int p = atomicAdd(&g_cur[d], 1);
            g_csr2[p] = make_int2(s, __float_as_int(__ldg(&g_dis[s])));
        }
    }
}

// ---------------- gemm1: fp32 f32x2 GEMM (x -> g_h1) fused with degree count ----------------
template <int K, int NO>
__global__ void __launch_bounds__(256) k_gemm1(const float* __restrict__ X,
                                               const float* __restrict__ W, int nrows,
                                               int gemm_blks, const void* __restrict__ ei) {
    constexpr int BM = 128, BK = 64;
    constexpr int TN = NO / 16;
    constexpr int NKC = K / BK;

    if ((int)blockIdx.x >= gemm_blks) {
        int cb = blockIdx.x - gemm_blks;
        int is64 = g_is64;
#pragma unroll
        for (int t = 0; t < 4; t++) {
            int e = cb * 1024 + t * 256 + threadIdx.x;
            if (e < N_EDGES) {
                int d = (int)load_idx(ei, (long long)N_EDGES + e, is64);
                if (d >= 0 && d < N_NODES) atomicAdd(&g_deg[d], 1);
            }
        }
        return;
    }

    __shared__ float xs[BK][BM];
    __shared__ float ws[BK][NO];
    float* Y = (float*)g_h1;

    const int tid = threadIdx.x;
    const int tr = tid >> 4;
    const int tc = tid & 15;
    const int row0 = blockIdx.x * BM;

    const int lr = tid & 127;
    const int lhalf = tid >> 7;
    const int gr_load = row0 + lr;
    const bool ld_ok = (gr_load < nrows);
    const float4* Xr = (const float4*)(X + (size_t)gr_load * K);

    uint64_t acc2[4][TN];
#pragma unroll
    for (int p = 0; p < 4; p++)
#pragma unroll
        for (int j = 0; j < TN; j++) acc2[p][j] = 0ull;

#pragma unroll
    for (int kc = 0; kc < NKC; kc++) {
        if (kc > 0) __syncthreads();
#pragma unroll
        for (int t = 0; t < 8; t++) {
            int c4 = lhalf * 8 + t;
            float4 v = ld_ok ? Xr[kc * (BK / 4) + c4] : make_float4(0.f, 0.f, 0.f, 0.f);
            int k0 = c4 * 4;
            xs[k0 + 0][lr] = v.x; xs[k0 + 1][lr] = v.y;
            xs[k0 + 2][lr] = v.z; xs[k0 + 3][lr] = v.w;
        }
        {
            const float4* W4 = (const float4*)(W + (size_t)kc * BK * NO);
            float4* ws4 = (float4*)ws;
#pragma unroll
            for (int t = tid; t < BK * NO / 4; t += 256) ws4[t] = W4[t];
        }
        __syncthreads();

#pragma unroll 8
        for (int k = 0; k < BK; k++) {
            ulonglong2 xlo = *(const ulonglong2*)&xs[k][tr * 8];
            ulonglong2 xhi = *(const ulonglong2*)&xs[k][tr * 8 + 4];
            uint64_t xp[4] = {xlo.x, xlo.y, xhi.x, xhi.y};
            float wv[TN];
            *(float4*)&wv[0] = *(const float4*)&ws[k][tc * 4];
            uint64_t wp[TN];
#pragma unroll
            for (int j = 0; j < TN; j++) {
                unsigned wb = __float_as_uint(wv[j]);
                asm("mov.b64 %0, {%1, %1};" : "=l"(wp[j]) : "r"(wb));
            }
#pragma unroll
            for (int p = 0; p < 4; p++)
#pragma unroll
                for (int j = 0; j < TN; j++)
                    asm("fma.rn.f32x2 %0, %1, %2, %0;"
                        : "+l"(acc2[p][j]) : "l"(xp[p]), "l"(wp[j]));
        }
    }

#pragma unroll
    for (int p = 0; p < 4; p++) {
        float accA[TN], accB[TN];
#pragma unroll
        for (int j = 0; j < TN; j++) {
            unsigned lo, hi;
            asm("mov.b64 {%0, %1}, %2;" : "=r"(lo), "=r"(hi) : "l"(acc2[p][j]));
            accA[j] = __uint_as_float(lo);
            accB[j] = __uint_as_float(hi);
        }
        int rA = row0 + tr * 8 + 2 * p;
        if (rA < nrows)
            *(float4*)&Y[(size_t)rA * NO + tc * 4] = make_float4(accA[0], accA[1], accA[2], accA[3]);
        if (rA + 1 < nrows)
            *(float4*)&Y[(size_t)(rA + 1) * NO + tc * 4] = make_float4(accB[0], accB[1], accB[2], accB[3]);
    }
}

// ---------------- standalone fp32 f32x2 GEMM (g_h2 -> g_h1) ----------------
template <int K, int NO>
__global__ void __launch_bounds__(256) k_gemm(const float* __restrict__ W, int nrows) {
    constexpr int BM = 128, BK = 64;
    constexpr int TN = NO / 16;
    constexpr int NKC = K / BK;
    __shared__ float xs[BK][BM];
    __shared__ float ws[BK][NO];

    const float* X = (const float*)g_h2;
    float* Y = (float*)g_h1;

    const int tid = threadIdx.x;
    const int tr = tid >> 4;
    const int tc = tid & 15;
    const int row0 = blockIdx.x * BM;

    const int lr = tid & 127;
    const int lhalf = tid >> 7;
    const int gr_load = row0 + lr;
    const bool ld_ok = (gr_load < nrows);
    const float4* Xr = (const float4*)(X + (size_t)gr_load * K);

    uint64_t acc2[4][TN];
#pragma unroll
    for (int p = 0; p < 4; p++)
#pragma unroll
        for (int j = 0; j < TN; j++) acc2[p][j] = 0ull;

#pragma unroll
    for (int kc = 0; kc < NKC; kc++) {
        if (kc > 0) __syncthreads();
#pragma unroll
        for (int t = 0; t < 8; t++) {
            int c4 = lhalf * 8 + t;
            float4 v = ld_ok ? Xr[kc * (BK / 4) + c4] : make_float4(0.f, 0.f, 0.f, 0.f);
            int k0 = c4 * 4;
            xs[k0 + 0][lr] = v.x; xs[k0 + 1][lr] = v.y;
            xs[k0 + 2][lr] = v.z; xs[k0 + 3][lr] = v.w;
        }
        {
            const float4* W4 = (const float4*)(W + (size_t)kc * BK * NO);
            float4* ws4 = (float4*)ws;
#pragma unroll
            for (int t = tid; t < BK * NO / 4; t += 256) ws4[t] = W4[t];
        }
        __syncthreads();

#pragma unroll 8
        for (int k = 0; k < BK; k++) {
            ulonglong2 xlo = *(const ulonglong2*)&xs[k][tr * 8];
            ulonglong2 xhi = *(const ulonglong2*)&xs[k][tr * 8 + 4];
            uint64_t xp[4] = {xlo.x, xlo.y, xhi.x, xhi.y};
            float wv[TN];
            if (TN == 4) {
                *(float4*)&wv[0] = *(const float4*)&ws[k][tc * 4];
            } else {
                *(float2*)&wv[0] = *(const float2*)&ws[k][tc * 2];
            }
            uint64_t wp[TN];
#pragma unroll
            for (int j = 0; j < TN; j++) {
                unsigned wb = __float_as_uint(wv[j]);
                asm("mov.b64 %0, {%1, %1};" : "=l"(wp[j]) : "r"(wb));
            }
#pragma unroll
            for (int p = 0; p < 4; p++)
#pragma unroll
                for (int j = 0; j < TN; j++)
                    asm("fma.rn.f32x2 %0, %1, %2, %0;"
                        : "+l"(acc2[p][j]) : "l"(xp[p]), "l"(wp[j]));
        }
    }

#pragma unroll
    for (int p = 0; p < 4; p++) {
        float accA[TN], accB[TN];
#pragma unroll
        for (int j = 0; j < TN; j++) {
            unsigned lo, hi;
            asm("mov.b64 {%0, %1}, %2;" : "=r"(lo), "=r"(hi) : "l"(acc2[p][j]));
            accA[j] = __uint_as_float(lo);
            accB[j] = __uint_as_float(hi);
        }
        int rA = row0 + tr * 8 + 2 * p;
        if (TN == 4) {
            if (rA < nrows)
                *(float4*)&Y[(size_t)rA * NO + tc * 4] = make_float4(accA[0], accA[1], accA[2], accA[3]);
            if (rA + 1 < nrows)
                *(float4*)&Y[(size_t)(rA + 1) * NO + tc * 4] = make_float4(accB[0], accB[1], accB[2], accB[3]);
        } else {
            if (rA < nrows)
                *(float2*)&Y[(size_t)rA * NO + tc * 2] = make_float2(accA[0], accA[1]);
            if (rA + 1 < nrows)
                *(float2*)&Y[(size_t)(rA + 1) * NO + tc * 2] = make_float2(accB[0], accB[1]);
        }
    }
}

// ---------------- aggregation with packed (src, dis) CSR ----------------
__global__ void k_agg64(const float* __restrict__ b) {
    int warp = (blockIdx.x * blockDim.x + threadIdx.x) >> 5;
    int lane = threadIdx.x & 31;
    if (warp >= N_NODES) return;
    const float* hin = (const float*)g_h1;
    float* hout = (float*)g_h2;

    int i = warp;
    float di = g_dis[i];
    int start = g_off[i];
    int cnt = g_deg[i];

    float ax = 0.f, ay = 0.f, bx = 0.f, by = 0.f;
    int j = 0;
    for (; j + 2 <= cnt; j += 2) {
        int2 e0 = __ldg(&g_csr2[start + j]);
        int2 e1 = __ldg(&g_csr2[start + j + 1]);
        float f0 = __int_as_float(e0.y);
        float f1 = __int_as_float(e1.y);
        float2 v0 = *(const float2*)(hin + (size_t)e0.x * 64 + 2 * lane);
        float2 v1 = *(const float2*)(hin + (size_t)e1.x * 64 + 2 * lane);
        ax = fmaf(f0, v0.x, ax); ay = fmaf(f0, v0.y, ay);
        bx = fmaf(f1, v1.x, bx); by = fmaf(f1, v1.y, by);
    }
    if (j < cnt) {
        int2 e0 = __ldg(&g_csr2[start + j]);
        float f0 = __int_as_float(e0.y);
        float2 v0 = *(const float2*)(hin + (size_t)e0.x * 64 + 2 * lane);
        ax = fmaf(f0, v0.x, ax); ay = fmaf(f0, v0.y, ay);
    }
    ax += bx; ay += by;

    float2 hi = *(const float2*)(hin + (size_t)i * 64 + 2 * lane);
    float2 bb = *(const float2*)(b + 2 * lane);
    float dii = di * di;
    float ox = fmaf(di, ax, fmaf(dii, hi.x, bb.x));
    float oy = fmaf(di, ay, fmaf(dii, hi.y, bb.y));
    *(float2*)(hout + (size_t)i * 64 + 2 * lane) = make_float2(fmaxf(ox, 0.f), fmaxf(oy, 0.f));
}

__global__ void k_agg32(const float* __restrict__ b) {
    int warp = (blockIdx.x * blockDim.x + threadIdx.x) >> 5;
    int lane = threadIdx.x & 31;
    if (warp >= N_NODES) return;
    const float* hin = (const float*)g_h1;
    float* hout = (float*)g_h2;

    int i = warp;
    float di = g_dis[i];
    int start = g_off[i];
    int cnt = g_deg[i];

    float a0 = 0.f, b0 = 0.f;
    int j = 0;
    for (; j + 2 <= cnt; j += 2) {
        int2 e0 = __ldg(&g_csr2[start + j]);
        int2 e1 = __ldg(&g_csr2[start + j + 1]);
        float f0 = __int_as_float(e0.y);
        float f1 = __int_as_float(e1.y);
        a0 = fmaf(f0, hin[(size_t)e0.x * 32 + lane], a0);
        b0 = fmaf(f1, hin[(size_t)e1.x * 32 + lane], b0);
    }
    if (j < cnt) {
        int2 e0 = __ldg(&g_csr2[start + j]);
        float f0 = __int_as_float(e0.y);
        a0 = fmaf(f0, hin[(size_t)e0.x * 32 + lane], a0);
    }
    a0 += b0;

    float o0 = fmaf(di, a0, fmaf(di * di, hin[(size_t)i * 32 + lane], b[lane]));
    hout[(size_t)i * 32 + lane] = fmaxf(o0, 0.0f);
}

// ---------------- pool + classifier (batch sorted) ----------------
__device__ __forceinline__ int lowerb(const void* a, int n, long long key, int is64) {
    int lo = 0, hi = n;
    while (lo < hi) {
        int mid = (lo + hi) >> 1;
        if (load_idx(a, mid, is64) < key) lo = mid + 1; else hi = mid;
    }
    return lo;
}

__global__ void k_pool(const void* __restrict__ batch,
                       const float* __restrict__ Wc1, const float* __restrict__ bc1,
                       const float* __restrict__ Wc2, const float* __restrict__ bc2,
                       float* __restrict__ out) {
    int warp = (blockIdx.x * blockDim.x + threadIdx.x) >> 5;
    int lane = threadIdx.x & 31;
    int wl = (threadIdx.x >> 5);
    if (warp >= N_GRAPHS) return;
    const float* h3 = (const float*)g_h2;
    int is64 = g_is64;

    long long g = warp;
    int start = lowerb(batch, N_NODES, g, is64);
    int end = lowerb(batch, N_NODES, g + 1, is64);

    float acc = 0.0f;
    for (int r = start; r < end; r++) acc += h3[(size_t)r * EMB + lane];
    float cnt = (float)(end - start);
    float emb = acc / fmaxf(cnt, 1.0f);

    __shared__ float sh[8][EMB];
    sh[wl][lane] = emb;
    __syncwarp();

    float partial = 0.0f;
    if (lane < 16) {
        float t = bc1[lane];
#pragma unroll
        for (int c = 0; c < EMB; c++) t = fmaf(sh[wl][c], Wc1[c * 16 + lane], t);
        t = fmaxf(t, 0.0f);
        partial = t * Wc2[lane];
    }
#pragma unroll
    for (int o = 8; o > 0; o >>= 1) partial += __shfl_down_sync(0xffffffffu, partial, o);
    if (lane == 0) out[g] = partial + bc2[0];
}

// ---------------- launch ----------------
extern "C" void kernel_launch(void* const* d_in, const int* in_sizes, int n_in,
                              void* d_out, int out_size) {
    const float* x     = (const float*)d_in[0];
    const void*  ei    = d_in[1];
    const void*  batch = d_in[2];
    const float* W1 = (const float*)d_in[3];  const float* b1 = (const float*)d_in[4];
    const float* W2 = (const float*)d_in[5];  const float* b2 = (const float*)d_in[6];
    const float* W3 = (const float*)d_in[7];  const float* b3 = (const float*)d_in[8];
    const float* Wc1 = (const float*)d_in[9]; const float* bc1 = (const float*)d_in[10];
    const float* Wc2 = (const float*)d_in[11]; const float* bc2 = (const float*)d_in[12];
    float* out = (float*)d_out;

    const int NB_N1024 = (N_NODES + 1023) / 1024;   // 196
    const int NB_E256  = (N_EDGES + 255) / 256;     // 4883
    const int NB_N256  = (N_NODES + 255) / 256;     // 782

    const int GEMM_BLKS  = (N_NODES + 127) / 128;        // 1563
    const int COUNT_BLKS = (N_EDGES + 1023) / 1024;      // 1221
    const int AGG_BLKS   = (N_NODES * 32 + 255) / 256;   // 25000

    // preprocessing (count fused into gemm1's grid; scan2 folded into scan3)
    k_zero_detect<<<NB_N1024, 1024>>>((const unsigned*)ei);
    k_gemm1<128, 64><<<GEMM_BLKS + COUNT_BLKS, 256>>>(x, W1, N_NODES, GEMM_BLKS, ei);
    k_scan1<<<NB_N1024, 1024>>>();
    k_scan3<<<NB_N256, 256>>>();
    k_fill_csr<<<NB_E256, 256>>>(ei);

    // layer 1 aggregation
    k_agg64<<<AGG_BLKS, 256>>>(b1);
    // layer 2: 64 -> 64
    k_gemm<64, 64><<<GEMM_BLKS, 256>>>(W2, N_NODES);
    k_agg64<<<AGG_BLKS, 256>>>(b2);
    // layer 3: 64 -> 32
    k_gemm<64, 32><<<GEMM_BLKS, 256>>>(W3, N_NODES);
    k_agg32<<<AGG_BLKS, 256>>>(b3);

    // pool + classifier
    k_pool<<<N_GRAPHS / 8, 256>>>(batch, Wc1, bc1, Wc2, bc2, out);
}

// round 14
// speedup vs baseline: 1.0801x; 1.0801x over previous
#include <cuda_runtime.h>
#include <math.h>
#include <cstdint>

#define N_NODES 200000
#define N_EDGES 1250000
#define N_GRAPHS 2048
#define IN_CH 128
#define HID 64
#define EMB 32

// ---------------- scratch (static device globals; no allocation) ----------------
__device__ int   g_is64;
__device__ int   g_deg[N_NODES];
__device__ float g_dis[N_NODES];
__device__ int   g_off[N_NODES];
__device__ int   g_cur[N_NODES];
__device__ int   g_csr[N_EDGES];
__device__ int   g_bsums[256];
__device__ __align__(16) float g_h1[(size_t)N_NODES * 64];
__device__ __align__(16) float g_h2[(size_t)N_NODES * 64];

__device__ __forceinline__ long long load_idx(const void* p, long long i, int is64) {
    if (is64) return ((const long long*)p)[i];
    return (long long)((const int*)p)[i];
}

// ---------------- zero degree + dtype detect (fused) ----------------
__global__ void k_zero_detect(const unsigned* __restrict__ ei_words) {
    int i = blockIdx.x * 1024 + threadIdx.x;
    if (i < N_NODES) g_deg[i] = 0;
    if (blockIdx.x == 0 && threadIdx.x < 128) {
        unsigned w = ei_words[2 * threadIdx.x + 1];
        unsigned any = __ballot_sync(0xffffffffu, w != 0u);
        __shared__ unsigned s_any[4];
        if ((threadIdx.x & 31) == 0) s_any[threadIdx.x >> 5] = any;
        __syncthreads();
        if (threadIdx.x == 0) {
            unsigned t = s_any[0] | s_any[1] | s_any[2] | s_any[3];
            g_is64 = t ? 0 : 1;
        }
    }
}

// ---------------- degree count (standalone; precedes scan1) ----------------
__global__ void k_count_deg(const void* __restrict__ ei) {
    int is64 = g_is64;
#pragma unroll
    for (int t = 0; t < 4; t++) {
        int e = blockIdx.x * 1024 + t * 256 + threadIdx.x;
        if (e < N_EDGES) {
            int d = (int)load_idx(ei, (long long)N_EDGES + e, is64);
            if (d >= 0 && d < N_NODES) atomicAdd(&g_deg[d], 1);
        }
    }
}

// ---------------- block inclusive scan ----------------
template <int NT>
__device__ __forceinline__ int block_inclusive_scan(int v, int tid) {
    int lane = tid & 31, w = tid >> 5;
    int x = v;
#pragma unroll
    for (int o = 1; o < 32; o <<= 1) {
        int y = __shfl_up_sync(0xffffffffu, x, o);
        if (lane >= o) x += y;
    }
    __shared__ int wsum[NT / 32];
    if (lane == 31) wsum[w] = x;
    __syncthreads();
    if (w == 0) {
        const int NW = NT / 32;
        int s = (lane < NW) ? wsum[lane] : 0;
#pragma unroll
        for (int o = 1; o < 32; o <<= 1) {
            int y = __shfl_up_sync(0xffffffffu, s, o);
            if (lane >= o) s += y;
        }
        if (lane < NW) wsum[lane] = s;
    }
    __syncthreads();
    return x + (w ? wsum[w - 1] : 0);
}

__global__ void k_scan1() {
    int idx = blockIdx.x * 1024 + threadIdx.x;
    int v = (idx < N_NODES) ? g_deg[idx] : 0;
    int incl = block_inclusive_scan<1024>(v, threadIdx.x);
    if (idx < N_NODES) g_off[idx] = incl - v;
    if (threadIdx.x == 1023) g_bsums[blockIdx.x] = incl;
}

// scan3': per-block inline prefix over bsums (scan2 folded in; measured 6.5us vs 9.5us)
__global__ void k_scan3() {
    const int pb = blockIdx.x >> 2;   // which 1024-chunk this 256-block lies in
    __shared__ int s_pre;
    if (threadIdx.x < 32) {
        int acc = 0;
        for (int t = threadIdx.x; t < pb; t += 32) acc += g_bsums[t];
#pragma unroll
        for (int o = 16; o > 0; o >>= 1) acc += __shfl_down_sync(0xffffffffu, acc, o);
        if (threadIdx.x == 0) s_pre = acc;
    }
    __syncthreads();
    int idx = blockIdx.x * 256 + threadIdx.x;
    if (idx < N_NODES) {
        int o = g_off[idx] + s_pre;
        g_off[idx] = o;
        g_cur[idx] = o;
        g_dis[idx] = rsqrtf(1.0f + (float)g_deg[idx]);
    }
}

// ---------------- gemm1: fp32 f32x2 GEMM (x -> g_h1) fused with CSR fill ----------------
template <int K, int NO>
__global__ void __launch_bounds__(256) k_gemm1(const float* __restrict__ X,
                                               const float* __restrict__ W, int nrows,
                                               int gemm_blks, const void* __restrict__ ei) {
    constexpr int BM = 128, BK = 64;
    constexpr int TN = NO / 16;
    constexpr int NKC = K / BK;

    if ((int)blockIdx.x >= gemm_blks) {
        // -------- CSR fill: 4 edges per thread (hidden under GEMM) --------
        int cb = blockIdx.x - gemm_blks;
        int is64 = g_is64;
#pragma unroll
        for (int t = 0; t < 4; t++) {
            int e = cb * 1024 + t * 256 + threadIdx.x;
            if (e < N_EDGES) {
                int s = (int)load_idx(ei, e, is64);
                int d = (int)load_idx(ei, (long long)N_EDGES + e, is64);
                if (d >= 0 && d < N_NODES && s >= 0 && s < N_NODES) {
                    int p = atomicAdd(&g_cur[d], 1);
                    g_csr[p] = s;
                }
            }
        }
        return;
    }

    __shared__ float xs[BK][BM];
    __shared__ float ws[BK][NO];
    float* Y = (float*)g_h1;

    const int tid = threadIdx.x;
    const int tr = tid >> 4;
    const int tc = tid & 15;
    const int row0 = blockIdx.x * BM;

    const int lr = tid & 127;
    const int lhalf = tid >> 7;
    const int gr_load = row0 + lr;
    const bool ld_ok = (gr_load < nrows);
    const float4* Xr = (const float4*)(X + (size_t)gr_load * K);

    uint64_t acc2[4][TN];
#pragma unroll
    for (int p = 0; p < 4; p++)
#pragma unroll
        for (int j = 0; j < TN; j++) acc2[p][j] = 0ull;

#pragma unroll
    for (int kc = 0; kc < NKC; kc++) {
        if (kc > 0) __syncthreads();
#pragma unroll
        for (int t = 0; t < 8; t++) {
            int c4 = lhalf * 8 + t;
            float4 v = ld_ok ? Xr[kc * (BK / 4) + c4] : make_float4(0.f, 0.f, 0.f, 0.f);
            int k0 = c4 * 4;
            xs[k0 + 0][lr] = v.x; xs[k0 + 1][lr] = v.y;
            xs[k0 + 2][lr] = v.z; xs[k0 + 3][lr] = v.w;
        }
        {
            const float4* W4 = (const float4*)(W + (size_t)kc * BK * NO);
            float4* ws4 = (float4*)ws;
#pragma unroll
            for (int t = tid; t < BK * NO / 4; t += 256) ws4[t] = W4[t];
        }
        __syncthreads();

#pragma unroll 8
        for (int k = 0; k < BK; k++) {
            ulonglong2 xlo = *(const ulonglong2*)&xs[k][tr * 8];
            ulonglong2 xhi = *(const ulonglong2*)&xs[k][tr * 8 + 4];
            uint64_t xp[4] = {xlo.x, xlo.y, xhi.x, xhi.y};
            float wv[TN];
            *(float4*)&wv[0] = *(const float4*)&ws[k][tc * 4];
            uint64_t wp[TN];
#pragma unroll
            for (int j = 0; j < TN; j++) {
                unsigned wb = __float_as_uint(wv[j]);
                asm("mov.b64 %0, {%1, %1};" : "=l"(wp[j]) : "r"(wb));
            }
#pragma unroll
            for (int p = 0; p < 4; p++)
#pragma unroll
                for (int j = 0; j < TN; j++)
                    asm("fma.rn.f32x2 %0, %1, %2, %0;"
                        : "+l"(acc2[p][j]) : "l"(xp[p]), "l"(wp[j]));
        }
    }

#pragma unroll
    for (int p = 0; p < 4; p++) {
        float accA[TN], accB[TN];
#pragma unroll
        for (int j = 0; j < TN; j++) {
            unsigned lo, hi;
            asm("mov.b64 {%0, %1}, %2;" : "=r"(lo), "=r"(hi) : "l"(acc2[p][j]));
            accA[j] = __uint_as_float(lo);
            accB[j] = __uint_as_float(hi);
        }
        int rA = row0 + tr * 8 + 2 * p;
        if (rA < nrows)
            *(float4*)&Y[(size_t)rA * NO + tc * 4] = make_float4(accA[0], accA[1], accA[2], accA[3]);
        if (rA + 1 < nrows)
            *(float4*)&Y[(size_t)(rA + 1) * NO + tc * 4] = make_float4(accB[0], accB[1], accB[2], accB[3]);
    }
}

// ---------------- standalone fp32 f32x2 GEMM (g_h2 -> g_h1) ----------------
template <int K, int NO>
__global__ void __launch_bounds__(256) k_gemm(const float* __restrict__ W, int nrows) {
    constexpr int BM = 128, BK = 64;
    constexpr int TN = NO / 16;
    constexpr int NKC = K / BK;
    __shared__ float xs[BK][BM];
    __shared__ float ws[BK][NO];

    const float* X = (const float*)g_h2;
    float* Y = (float*)g_h1;

    const int tid = threadIdx.x;
    const int tr = tid >> 4;
    const int tc = tid & 15;
    const int row0 = blockIdx.x * BM;

    const int lr = tid & 127;
    const int lhalf = tid >> 7;
    const int gr_load = row0 + lr;
    const bool ld_ok = (gr_load < nrows);
    const float4* Xr = (const float4*)(X + (size_t)gr_load * K);

    uint64_t acc2[4][TN];
#pragma unroll
    for (int p = 0; p < 4; p++)
#pragma unroll
        for (int j = 0; j < TN; j++) acc2[p][j] = 0ull;

#pragma unroll
    for (int kc = 0; kc < NKC; kc++) {
        if (kc > 0) __syncthreads();
#pragma unroll
        for (int t = 0; t < 8; t++) {
            int c4 = lhalf * 8 + t;
            float4 v = ld_ok ? Xr[kc * (BK / 4) + c4] : make_float4(0.f, 0.f, 0.f, 0.f);
            int k0 = c4 * 4;
            xs[k0 + 0][lr] = v.x; xs[k0 + 1][lr] = v.y;
            xs[k0 + 2][lr] = v.z; xs[k0 + 3][lr] = v.w;
        }
        {
            const float4* W4 = (const float4*)(W + (size_t)kc * BK * NO);
            float4* ws4 = (float4*)ws;
#pragma unroll
            for (int t = tid; t < BK * NO / 4; t += 256) ws4[t] = W4[t];
        }
        __syncthreads();

#pragma unroll 8
        for (int k = 0; k < BK; k++) {
            ulonglong2 xlo = *(const ulonglong2*)&xs[k][tr * 8];
            ulonglong2 xhi = *(const ulonglong2*)&xs[k][tr * 8 + 4];
            uint64_t xp[4] = {xlo.x, xlo.y, xhi.x, xhi.y};
            float wv[TN];
            if (TN == 4) {
                *(float4*)&wv[0] = *(const float4*)&ws[k][tc * 4];
            } else {
                *(float2*)&wv[0] = *(const float2*)&ws[k][tc * 2];
            }
            uint64_t wp[TN];
#pragma unroll
            for (int j = 0; j < TN; j++) {
                unsigned wb = __float_as_uint(wv[j]);
                asm("mov.b64 %0, {%1, %1};" : "=l"(wp[j]) : "r"(wb));
            }
#pragma unroll
            for (int p = 0; p < 4; p++)
#pragma unroll
                for (int j = 0; j < TN; j++)
                    asm("fma.rn.f32x2 %0, %1, %2, %0;"
                        : "+l"(acc2[p][j]) : "l"(xp[p]), "l"(wp[j]));
        }
    }

#pragma unroll
    for (int p = 0; p < 4; p++) {
        float accA[TN], accB[TN];
#pragma unroll
        for (int j = 0; j < TN; j++) {
            unsigned lo, hi;
            asm("mov.b64 {%0, %1}, %2;" : "=r"(lo), "=r"(hi) : "l"(acc2[p][j]));
            accA[j] = __uint_as_float(lo);
            accB[j] = __uint_as_float(hi);
        }
        int rA = row0 + tr * 8 + 2 * p;
        if (TN == 4) {
            if (rA < nrows)
                *(float4*)&Y[(size_t)rA * NO + tc * 4] = make_float4(accA[0], accA[1], accA[2], accA[3]);
            if (rA + 1 < nrows)
                *(float4*)&Y[(size_t)(rA + 1) * NO + tc * 4] = make_float4(accB[0], accB[1], accB[2], accB[3]);
        } else {
            if (rA < nrows)
                *(float2*)&Y[(size_t)rA * NO + tc * 2] = make_float2(accA[0], accA[1]);
            if (rA + 1 < nrows)
                *(float2*)&Y[(size_t)(rA + 1) * NO + tc * 2] = make_float2(accB[0], accB[1]);
        }
    }
}

// ---------------- aggregation (R11 proven: int CSR + separate dis) ----------------
__global__ void k_agg64(const float* __restrict__ b) {
    int warp = (blockIdx.x * blockDim.x + threadIdx.x) >> 5;
    int lane = threadIdx.x & 31;
    if (warp >= N_NODES) return;
    const float* hin = (const float*)g_h1;
    float* hout = (float*)g_h2;

    int i = warp;
    float di = g_dis[i];
    int start = g_off[i];
    int cnt = g_deg[i];

    float ax = 0.f, ay = 0.f, bx = 0.f, by = 0.f;
    int j = 0;
    for (; j + 2 <= cnt; j += 2) {
        int s0 = __ldg(&g_csr[start + j]);
        int s1 = __ldg(&g_csr[start + j + 1]);
        float f0 = __ldg(&g_dis[s0]);
        float f1 = __ldg(&g_dis[s1]);
        float2 v0 = *(const float2*)(hin + (size_t)s0 * 64 + 2 * lane);
        float2 v1 = *(const float2*)(hin + (size_t)s1 * 64 + 2 * lane);
        ax = fmaf(f0, v0.x, ax); ay = fmaf(f0, v0.y, ay);
        bx = fmaf(f1, v1.x, bx); by = fmaf(f1, v1.y, by);
    }
    if (j < cnt) {
        int s0 = __ldg(&g_csr[start + j]);
        float f0 = __ldg(&g_dis[s0]);
        float2 v0 = *(const float2*)(hin + (size_t)s0 * 64 + 2 * lane);
        ax = fmaf(f0, v0.x, ax); ay = fmaf(f0, v0.y, ay);
    }
    ax += bx; ay += by;

    float2 hi = *(const float2*)(hin + (size_t)i * 64 + 2 * lane);
    float2 bb = *(const float2*)(b + 2 * lane);
    float dii = di * di;
    float ox = fmaf(di, ax, fmaf(dii, hi.x, bb.x));
    float oy = fmaf(di, ay, fmaf(dii, hi.y, bb.y));
    *(float2*)(hout + (size_t)i * 64 + 2 * lane) = make_float2(fmaxf(ox, 0.f), fmaxf(oy, 0.f));
}

__global__ void k_agg32(const float* __restrict__ b) {
    int warp = (blockIdx.x * blockDim.x + threadIdx.x) >> 5;
    int lane = threadIdx.x & 31;
    if (warp >= N_NODES) return;
    const float* hin = (const float*)g_h1;
    float* hout = (float*)g_h2;

    int i = warp;
    float di = g_dis[i];
    int start = g_off[i];
    int cnt = g_deg[i];

    float a0 = 0.f, b0 = 0.f;
    int j = 0;
    for (; j + 2 <= cnt; j += 2) {
        int s0 = __ldg(&g_csr[start + j]);
        int s1 = __ldg(&g_csr[start + j + 1]);
        float f0 = __ldg(&g_dis[s0]);
        float f1 = __ldg(&g_dis[s1]);
        a0 = fmaf(f0, hin[(size_t)s0 * 32 + lane], a0);
        b0 = fmaf(f1, hin[(size_t)s1 * 32 + lane], b0);
    }
    if (j < cnt) {
        int s0 = __ldg(&g_csr[start + j]);
        float f0 = __ldg(&g_dis[s0]);
        a0 = fmaf(f0, hin[(size_t)s0 * 32 + lane], a0);
    }
    a0 += b0;

    float o0 = fmaf(di, a0, fmaf(di * di, hin[(size_t)i * 32 + lane], b[lane]));
    hout[(size_t)i * 32 + lane] = fmaxf(o0, 0.0f);
}

// ---------------- pool + classifier (batch sorted) ----------------
__device__ __forceinline__ int lowerb(const void* a, int n, long long key, int is64) {
    int lo = 0, hi = n;
    while (lo < hi) {
        int mid = (lo + hi) >> 1;
        if (load_idx(a, mid, is64) < key) lo = mid + 1; else hi = mid;
    }
    return lo;
}

__global__ void k_pool(const void* __restrict__ batch,
                       const float* __restrict__ Wc1, const float* __restrict__ bc1,
                       const float* __restrict__ Wc2, const float* __restrict__ bc2,
                       float* __restrict__ out) {
    int warp = (blockIdx.x * blockDim.x + threadIdx.x) >> 5;
    int lane = threadIdx.x & 31;
    int wl = (threadIdx.x >> 5);
    if (warp >= N_GRAPHS) return;
    const float* h3 = (const float*)g_h2;
    int is64 = g_is64;

    long long g = warp;
    int start = lowerb(batch, N_NODES, g, is64);
    int end = lowerb(batch, N_NODES, g + 1, is64);

    float acc = 0.0f;
    for (int r = start; r < end; r++) acc += h3[(size_t)r * EMB + lane];
    float cnt = (float)(end - start);
    float emb = acc / fmaxf(cnt, 1.0f);

    __shared__ float sh[8][EMB];
    sh[wl][lane] = emb;
    __syncwarp();

    float partial = 0.0f;
    if (lane < 16) {
        float t = bc1[lane];
#pragma unroll
        for (int c = 0; c < EMB; c++) t = fmaf(sh[wl][c], Wc1[c * 16 + lane], t);
        t = fmaxf(t, 0.0f);
        partial = t * Wc2[lane];
    }
#pragma unroll
    for (int o = 8; o > 0; o >>= 1) partial += __shfl_down_sync(0xffffffffu, partial, o);
    if (lane == 0) out[g] = partial + bc2[0];
}

// ---------------- launch ----------------
extern "C" void kernel_launch(void* const* d_in, const int* in_sizes, int n_in,
                              void* d_out, int out_size) {
    const float* x     = (const float*)d_in[0];
    const void*  ei    = d_in[1];
    const void*  batch = d_in[2];
    const float* W1 = (const float*)d_in[3];  const float* b1 = (const float*)d_in[4];
    const float* W2 = (const float*)d_in[5];  const float* b2 = (const float*)d_in[6];
    const float* W3 = (const float*)d_in[7];  const float* b3 = (const float*)d_in[8];
    const float* Wc1 = (const float*)d_in[9]; const float* bc1 = (const float*)d_in[10];
    const float* Wc2 = (const float*)d_in[11]; const float* bc2 = (const float*)d_in[12];
    float* out = (float*)d_out;

    const int NB_N1024 = (N_NODES + 1023) / 1024;   // 196
    const int NB_N256  = (N_NODES + 255) / 256;     // 782

    const int GEMM_BLKS = (N_NODES + 127) / 128;        // 1563
    const int EDGE_BLKS = (N_EDGES + 1023) / 1024;      // 1221 (4 edges/thread)
    const int AGG_BLKS  = (N_NODES * 32 + 255) / 256;   // 25000

    // preprocessing: zero+detect -> count -> scan1 -> scan3' (scan2 folded)
    k_zero_detect<<<NB_N1024, 1024>>>((const unsigned*)ei);
    k_count_deg<<<EDGE_BLKS, 256>>>(ei);
    k_scan1<<<NB_N1024, 1024>>>();
    k_scan3<<<NB_N256, 256>>>();

    // layer 1 GEMM with CSR fill hidden in its grid
    k_gemm1<128, 64><<<GEMM_BLKS + EDGE_BLKS, 256>>>(x, W1, N_NODES, GEMM_BLKS, ei);

    // layer 1 aggregation
    k_agg64<<<AGG_BLKS, 256>>>(b1);
    // layer 2: 64 -> 64
    k_gemm<64, 64><<<GEMM_BLKS, 256>>>(W2, N_NODES);
    k_agg64<<<AGG_BLKS, 256>>>(b2);
    // layer 3: 64 -> 32
    k_gemm<64, 32><<<GEMM_BLKS, 256>>>(W3, N_NODES);
    k_agg32<<<AGG_BLKS, 256>>>(b3);

    // pool + classifier
    k_pool<<<N_GRAPHS / 8, 256>>>(batch, Wc1, bc1, Wc2, bc2, out);
}